// round 1
// baseline (speedup 1.0000x reference)
#include <cuda_runtime.h>
#include <math.h>

// Problem constants
#define BB    8
#define CC    512
#define HH    56
#define WW_   56
#define HWSZ  3136
#define WS_   7
#define SS_   3
#define NH_   16
#define HD_   32
#define T_    49
#define NW_   64
#define BW_   512          // BB * NW_
#define NTOK  25088        // BW_ * T_
#define L_    64

// ---------------- scratch (device globals; no runtime alloc) ----------------
__device__ float g_vec [BW_ * CC];          // gelu(vector@tm_w+b)   [B*L, C]
__device__ float g_tok [NTOK * CC];         // unfolded rolled visual [Bw*T, C]
__device__ float g_qkv [NTOK * 3 * CC];     // qkv projection
__device__ float g_o1  [NTOK * CC];         // window-attn output
__device__ float g_w2  [NTOK * CC];         // wproj output
__device__ float g_skipa[NTOK * CC];        // skip1 in [B, HW, C]
__device__ float g_pq  [NTOK * CC];         // CA query tokens [Bw*T, C]
__device__ float g_q2  [NTOK * CC];
__device__ float g_k2  [BW_ * CC];          // [B*L, C]
__device__ float g_v2  [BW_ * CC];
__device__ float g_co1 [NTOK * CC];
__device__ float g_co2 [NTOK * CC];
__device__ float g_skip2[NTOK * CC];        // skip2 in [B, HW, C]
__device__ float g_ffh [NTOK * 4 * CC];
__device__ float g_ffo [NTOK * CC];
__device__ float g_bias[NH_ * T_ * T_];

// ---------------- helpers ----------------
__device__ __forceinline__ float gelu_exact(float x) {
    return 0.5f * x * (1.0f + erff(x * 0.70710678118654752f));
}

// block-wide mean/rstd over n values (256 threads), s/ss are per-thread partials
__device__ __forceinline__ void block_meanvar(float s, float ss, int n,
                                              float* mu, float* rstd) {
    #pragma unroll
    for (int o = 16; o > 0; o >>= 1) {
        s  += __shfl_down_sync(0xffffffffu, s,  o);
        ss += __shfl_down_sync(0xffffffffu, ss, o);
    }
    __shared__ float rs[8], rss[8], res[2];
    int lane = threadIdx.x & 31, wid = threadIdx.x >> 5;
    if (lane == 0) { rs[wid] = s; rss[wid] = ss; }
    __syncthreads();
    if (threadIdx.x == 0) {
        float S = 0.f, SS2 = 0.f;
        #pragma unroll
        for (int i = 0; i < 8; i++) { S += rs[i]; SS2 += rss[i]; }
        float m = S / n;
        float var = SS2 / n - m * m;
        res[0] = m; res[1] = rsqrtf(var + 1e-5f);
    }
    __syncthreads();
    *mu = res[0]; *rstd = res[1];
}

// ---------------- SGEMM: C[M,N] = epi(A[M,K] @ B[K,N](ldb) + bias) ----------
// Requires M%128==0, N%128==0, K%8==0, all float4-aligned.
#define EPI_NONE  0
#define EPI_GELU  1
#define EPI_SCALE 2

template <int EPI>
__global__ __launch_bounds__(256)
void sgemm(const float* __restrict__ A, const float* __restrict__ Bm,
           const float* __restrict__ bias, float* __restrict__ C,
           int M, int N, int K, int ldb, float alpha) {
    __shared__ __align__(16) float As[8][128];
    __shared__ __align__(16) float Bs[8][128];
    const int tid = threadIdx.x;
    const int m0 = blockIdx.y * 128;
    const int n0 = blockIdx.x * 128;
    const int tx = tid & 15, ty = tid >> 4;

    const int aRow = tid >> 1;           // 0..127
    const int aCol = (tid & 1) * 4;      // 0 or 4
    const int bRow = tid >> 5;           // 0..7
    const int bCol = (tid & 31) * 4;     // 0..124

    const float* Ap = A + (size_t)(m0 + aRow) * K + aCol;
    const float* Bp = Bm + (size_t)bRow * ldb + n0 + bCol;

    float acc[8][8];
    #pragma unroll
    for (int i = 0; i < 8; i++)
        #pragma unroll
        for (int j = 0; j < 8; j++) acc[i][j] = 0.f;

    for (int k0 = 0; k0 < K; k0 += 8) {
        float4 a4 = *(const float4*)(Ap + k0);
        float4 b4 = *(const float4*)(Bp + (size_t)k0 * ldb);
        As[aCol + 0][aRow] = a4.x;
        As[aCol + 1][aRow] = a4.y;
        As[aCol + 2][aRow] = a4.z;
        As[aCol + 3][aRow] = a4.w;
        *(float4*)&Bs[bRow][bCol] = b4;
        __syncthreads();
        #pragma unroll
        for (int kk = 0; kk < 8; kk++) {
            float af[8], bf[8];
            #pragma unroll
            for (int i = 0; i < 8; i++) af[i] = As[kk][ty * 8 + i];
            #pragma unroll
            for (int j = 0; j < 8; j++) bf[j] = Bs[kk][tx * 8 + j];
            #pragma unroll
            for (int i = 0; i < 8; i++)
                #pragma unroll
                for (int j = 0; j < 8; j++) acc[i][j] += af[i] * bf[j];
        }
        __syncthreads();
    }

    #pragma unroll
    for (int i = 0; i < 8; i++) {
        int row = m0 + ty * 8 + i;
        #pragma unroll
        for (int j = 0; j < 8; j += 4) {
            int col = n0 + tx * 8 + j;
            float4 o;
            float* op = (float*)&o;
            #pragma unroll
            for (int q = 0; q < 4; q++) {
                float v = acc[i][j + q] + bias[col + q];
                if (EPI == EPI_GELU)  v = gelu_exact(v);
                if (EPI == EPI_SCALE) v = v * alpha;
                op[q] = v;
            }
            *(float4*)&C[(size_t)row * N + col] = o;
        }
    }
}

// ---------------- relative-position bias precompute ----------------
__global__ void bias_kernel(const float* __restrict__ w1, const float* __restrict__ b1,
                            const float* __restrict__ w2, const float* __restrict__ b2) {
    int pair = blockIdx.x;             // 0..2400  (q*49+k)
    int q = pair / T_, k = pair % T_;
    float d0 = (float)(q / WS_ - k / WS_);
    float d1 = (float)(q % WS_ - k % WS_);
    float r0 = (d0 > 0.f ? 1.f : (d0 < 0.f ? -1.f : 0.f)) * log1pf(fabsf(d0));
    float r1 = (d1 > 0.f ? 1.f : (d1 < 0.f ? -1.f : 0.f)) * log1pf(fabsf(d1));
    int tid = threadIdx.x;             // 256
    __shared__ float hbuf[256];
    float hv = r0 * w1[tid] + r1 * w1[256 + tid] + b1[tid];
    hbuf[tid] = fmaxf(hv, 0.f);
    __syncthreads();
    if (tid < NH_) {
        float s = b2[tid];
        #pragma unroll 8
        for (int j = 0; j < 256; j++) s += hbuf[j] * w2[j * NH_ + tid];
        g_bias[tid * (T_ * T_) + pair] = s;
    }
}

// ---------------- roll(-3,-3) + unfold into token rows ----------------
__global__ __launch_bounds__(256)
void unfold_kernel(const float* __restrict__ visual) {
    int r = blockIdx.x;                // 0..25087 = bw*49+t
    int bw = r / T_, t = r % T_;
    int b = bw / NW_, win = bw % NW_, wh = win >> 3, ww = win & 7;
    int h = (wh * WS_ + t / WS_ + SS_) % HH;
    int w = (ww * WS_ + t % WS_ + SS_) % WW_;
    int hw = h * WW_ + w;
    for (int c = threadIdx.x; c < CC; c += 256)
        g_tok[(size_t)r * CC + c] = visual[(size_t)(b * CC + c) * HWSZ + hw];
}

// ---------------- window attention (cosine attn + bias + shift mask) --------
__global__ __launch_bounds__(256)
void win_attn(const float* __restrict__ tau) {
    int bw = blockIdx.x >> 4;
    int hh = blockIdx.x & 15;
    int tid = threadIdx.x;

    __shared__ float sq[T_ * HD_], sk[T_ * HD_], sv[T_ * HD_];
    __shared__ float ss[T_ * 50];
    __shared__ float nq[T_], nk[T_];
    __shared__ int   rg[T_];

    size_t base = (size_t)(bw * T_) * (3 * CC);
    for (int idx = tid; idx < T_ * HD_; idx += 256) {
        int t = idx / HD_, d = idx % HD_;
        size_t ro = base + (size_t)t * (3 * CC) + hh * HD_ + d;
        sq[idx] = g_qkv[ro];
        sk[idx] = g_qkv[ro + CC];
        sv[idx] = g_qkv[ro + 2 * CC];
    }
    int win = bw & 63, wh = win >> 3, ww = win & 7;
    if (tid < T_) {
        int row = wh * WS_ + tid / WS_;
        int col = ww * WS_ + tid % WS_;
        int rh = row < 49 ? 0 : (row < 53 ? 1 : 2);
        int rw = col < 49 ? 0 : (col < 53 ? 1 : 2);
        rg[tid] = rh * 3 + rw;
    }
    __syncthreads();

    if (tid < T_) {
        float s1 = 0.f, s2 = 0.f;
        #pragma unroll
        for (int d = 0; d < HD_; d++) {
            float a = sq[tid * HD_ + d], b = sk[tid * HD_ + d];
            s1 += a * a; s2 += b * b;
        }
        nq[tid] = sqrtf(s1); nk[tid] = sqrtf(s2);
    }
    __syncthreads();

    float tauh = fmaxf(tau[hh], 0.01f);
    const float* bh = &g_bias[hh * (T_ * T_)];
    for (int idx = tid; idx < T_ * T_; idx += 256) {
        int q = idx / T_, k = idx % T_;
        float dot = 0.f;
        #pragma unroll
        for (int d = 0; d < HD_; d++) dot += sq[q * HD_ + d] * sk[k * HD_ + d];
        float s = dot / fmaxf(nq[q] * nk[k], 1e-6f) / tauh + bh[idx];
        if (rg[q] != rg[k]) s -= 100.0f;
        ss[q * 50 + k] = s;
    }
    __syncthreads();

    if (tid < T_) {
        float m = -1e30f;
        for (int k = 0; k < T_; k++) m = fmaxf(m, ss[tid * 50 + k]);
        float sum = 0.f;
        for (int k = 0; k < T_; k++) {
            float e = expf(ss[tid * 50 + k] - m);
            ss[tid * 50 + k] = e; sum += e;
        }
        float inv = 1.f / sum;
        for (int k = 0; k < T_; k++) ss[tid * 50 + k] *= inv;
    }
    __syncthreads();

    for (int idx = tid; idx < T_ * HD_; idx += 256) {
        int t = idx / HD_, d = idx % HD_;
        float acc = 0.f;
        #pragma unroll
        for (int k = 0; k < T_; k++) acc += ss[t * 50 + k] * sv[k * HD_ + d];
        g_o1[(size_t)(bw * T_ + t) * CC + hh * HD_ + d] = acc;
    }
}

// ---------------- fold+roll(+3) + LN1 + residual; also emit CA query tokens -
__global__ __launch_bounds__(256)
void merge_ln1(const float* __restrict__ visual,
               const float* __restrict__ g, const float* __restrict__ bt) {
    int pos = blockIdx.x;              // b*3136 + h*56 + w
    int b = pos / HWSZ, hw = pos % HWSZ;
    int h = hw / WW_, w = hw % WW_;
    int hp = (h + HH - SS_) % HH, wp = (w + WW_ - SS_) % WW_;
    int rm = (b * NW_ + (hp / WS_) * 8 + (wp / WS_)) * T_ + (hp % WS_) * WS_ + (wp % WS_);

    __shared__ float x[CC];
    int tid = threadIdx.x;
    float s = 0.f, ss2 = 0.f;
    for (int c = tid; c < CC; c += 256) {
        float v = g_w2[(size_t)rm * CC + c];
        x[c] = v; s += v; ss2 += v * v;
    }
    float mu, rstd;
    block_meanvar(s, ss2, CC, &mu, &rstd);
    for (int c = tid; c < CC; c += 256) {
        float v = (x[c] - mu) * rstd * g[c] + bt[c]
                + visual[(size_t)(b * CC + c) * HWSZ + hw];
        g_skipa[(size_t)pos * CC + c] = v;
        g_pq  [(size_t)rm  * CC + c] = v;   // unfold(roll(skip,-3)) row == rm
    }
}

// ---------------- cross attention ----------------
__global__ __launch_bounds__(256)
void ca_attn() {
    int bw = blockIdx.x >> 4;
    int hh = blockIdx.x & 15;
    int bkv = bw & 7;                  // kv[i] = vec[i % B]
    int tid = threadIdx.x;

    __shared__ float sq[T_ * HD_], sk[L_ * HD_], sv[L_ * HD_];
    __shared__ float ss[T_ * 65];

    for (int idx = tid; idx < T_ * HD_; idx += 256) {
        int t = idx / HD_, d = idx % HD_;
        sq[idx] = g_q2[(size_t)(bw * T_ + t) * CC + hh * HD_ + d];
    }
    for (int idx = tid; idx < L_ * HD_; idx += 256) {
        int l = idx / HD_, d = idx % HD_;
        size_t ro = (size_t)(bkv * L_ + l) * CC + hh * HD_ + d;
        sk[idx] = g_k2[ro];
        sv[idx] = g_v2[ro];
    }
    __syncthreads();

    for (int idx = tid; idx < T_ * L_; idx += 256) {
        int q = idx / L_, l = idx % L_;
        float dot = 0.f;
        #pragma unroll
        for (int d = 0; d < HD_; d++) dot += sq[q * HD_ + d] * sk[l * HD_ + d];
        ss[q * 65 + l] = dot;          // q already scaled by HD^-0.5
    }
    __syncthreads();

    if (tid < T_) {
        float m = -1e30f;
        for (int l = 0; l < L_; l++) m = fmaxf(m, ss[tid * 65 + l]);
        float sum = 0.f;
        for (int l = 0; l < L_; l++) {
            float e = expf(ss[tid * 65 + l] - m);
            ss[tid * 65 + l] = e; sum += e;
        }
        float inv = 1.f / sum;
        for (int l = 0; l < L_; l++) ss[tid * 65 + l] *= inv;
    }
    __syncthreads();

    for (int idx = tid; idx < T_ * HD_; idx += 256) {
        int t = idx / HD_, d = idx % HD_;
        float acc = 0.f;
        #pragma unroll
        for (int l = 0; l < L_; l++) acc += ss[t * 65 + l] * sv[l * HD_ + d];
        g_co1[(size_t)(bw * T_ + t) * CC + hh * HD_ + d] = acc;
    }
}

// ---------------- LN2 + fold+roll(+3) + residual → skip2 [B,HW,C] -----------
__global__ __launch_bounds__(256)
void ca_ln2(const float* __restrict__ g, const float* __restrict__ bt) {
    int r = blockIdx.x;                // bw*49 + t
    int bw = r / T_, t = r % T_;
    int b = bw / NW_, win = bw % NW_, wh = win >> 3, ww = win & 7;
    int h = (wh * WS_ + t / WS_ + SS_) % HH;
    int w = (ww * WS_ + t % WS_ + SS_) % WW_;
    int pos = b * HWSZ + h * WW_ + w;

    __shared__ float x[CC];
    int tid = threadIdx.x;
    float s = 0.f, ss2 = 0.f;
    for (int c = tid; c < CC; c += 256) {
        float v = g_co2[(size_t)r * CC + c];
        x[c] = v; s += v; ss2 += v * v;
    }
    float mu, rstd;
    block_meanvar(s, ss2, CC, &mu, &rstd);
    for (int c = tid; c < CC; c += 256) {
        float v = (x[c] - mu) * rstd * g[c] + bt[c];
        g_skip2[(size_t)pos * CC + c] = v + g_skipa[(size_t)pos * CC + c];
    }
}

// ---------------- LN3(ff) + skip2, write [B,C,H,W] ----------------
__global__ __launch_bounds__(256)
void final_kernel(float* __restrict__ out,
                  const float* __restrict__ g, const float* __restrict__ bt) {
    int pos = blockIdx.x;              // b*3136 + hw
    int b = pos / HWSZ, hw = pos % HWSZ;

    __shared__ float x[CC];
    int tid = threadIdx.x;
    float s = 0.f, ss2 = 0.f;
    for (int c = tid; c < CC; c += 256) {
        float v = g_ffo[(size_t)pos * CC + c];
        x[c] = v; s += v; ss2 += v * v;
    }
    float mu, rstd;
    block_meanvar(s, ss2, CC, &mu, &rstd);
    for (int c = tid; c < CC; c += 256) {
        float v = (x[c] - mu) * rstd * g[c] + bt[c];
        out[(size_t)(b * CC + c) * HWSZ + hw] = g_skip2[(size_t)pos * CC + c] + v;
    }
}

// ---------------- launch ----------------
extern "C" void kernel_launch(void* const* d_in, const int* in_sizes, int n_in,
                              void* d_out, int out_size) {
    const float* visual   = (const float*)d_in[0];
    const float* vector   = (const float*)d_in[1];
    const float* tm_w     = (const float*)d_in[2];
    const float* tm_b     = (const float*)d_in[3];
    const float* ln1_g    = (const float*)d_in[4];
    const float* ln1_b    = (const float*)d_in[5];
    const float* ln2_g    = (const float*)d_in[6];
    const float* ln2_b    = (const float*)d_in[7];
    const float* ln3_g    = (const float*)d_in[8];
    const float* ln3_b    = (const float*)d_in[9];
    const float* qkv_w    = (const float*)d_in[10];
    const float* qkv_b    = (const float*)d_in[11];
    const float* wproj_w  = (const float*)d_in[12];
    const float* wproj_b  = (const float*)d_in[13];
    const float* meta_w1  = (const float*)d_in[14];
    const float* meta_b1  = (const float*)d_in[15];
    const float* meta_w2  = (const float*)d_in[16];
    const float* meta_b2  = (const float*)d_in[17];
    const float* tau      = (const float*)d_in[18];
    const float* ca_in_w  = (const float*)d_in[19];
    const float* ca_in_b  = (const float*)d_in[20];
    const float* ca_out_w = (const float*)d_in[21];
    const float* ca_out_b = (const float*)d_in[22];
    const float* ff_w1    = (const float*)d_in[23];
    const float* ff_b1    = (const float*)d_in[24];
    const float* ff_w2    = (const float*)d_in[25];
    const float* ff_b2    = (const float*)d_in[26];
    float* out = (float*)d_out;

    float* vec;   cudaGetSymbolAddress((void**)&vec,   g_vec);
    float* tok;   cudaGetSymbolAddress((void**)&tok,   g_tok);
    float* qkv;   cudaGetSymbolAddress((void**)&qkv,   g_qkv);
    float* o1;    cudaGetSymbolAddress((void**)&o1,    g_o1);
    float* w2;    cudaGetSymbolAddress((void**)&w2,    g_w2);
    float* pq;    cudaGetSymbolAddress((void**)&pq,    g_pq);
    float* q2;    cudaGetSymbolAddress((void**)&q2,    g_q2);
    float* k2;    cudaGetSymbolAddress((void**)&k2,    g_k2);
    float* v2;    cudaGetSymbolAddress((void**)&v2,    g_v2);
    float* co1;   cudaGetSymbolAddress((void**)&co1,   g_co1);
    float* co2;   cudaGetSymbolAddress((void**)&co2,   g_co2);
    float* sk2;   cudaGetSymbolAddress((void**)&sk2,   g_skip2);
    float* ffh;   cudaGetSymbolAddress((void**)&ffh,   g_ffh);
    float* ffo;   cudaGetSymbolAddress((void**)&ffo,   g_ffo);

    // precompute rel-pos bias
    bias_kernel<<<T_ * T_, 256>>>(meta_w1, meta_b1, meta_w2, meta_b2);

    // vec = gelu(vector @ tm_w + tm_b)     [512,512] K=256
    sgemm<EPI_GELU><<<dim3(4, 4), 256>>>(vector, tm_w, tm_b, vec, 512, 512, 256, 512, 0.f);

    // K2/V2 (only B distinct kv sets)
    sgemm<EPI_NONE><<<dim3(4, 4), 256>>>(vec, ca_in_w + CC,     ca_in_b + CC,     k2, 512, 512, 512, 3 * CC, 0.f);
    sgemm<EPI_NONE><<<dim3(4, 4), 256>>>(vec, ca_in_w + 2 * CC, ca_in_b + 2 * CC, v2, 512, 512, 512, 3 * CC, 0.f);

    // tokens
    unfold_kernel<<<NTOK, 256>>>(visual);

    // qkv projection  [25088,1536]
    sgemm<EPI_NONE><<<dim3(12, 196), 256>>>(tok, qkv_w, qkv_b, qkv, NTOK, 3 * CC, CC, 3 * CC, 0.f);

    // window attention
    win_attn<<<BW_ * NH_, 256>>>(tau);

    // wproj
    sgemm<EPI_NONE><<<dim3(4, 196), 256>>>(o1, wproj_w, wproj_b, w2, NTOK, CC, CC, CC, 0.f);

    // fold+roll + LN1 + residual, emit pq
    merge_ln1<<<BB * HWSZ, 256>>>(visual, ln1_g, ln1_b);

    // q2 = (pq @ wq + bq) * HD^-0.5
    sgemm<EPI_SCALE><<<dim3(4, 196), 256>>>(pq, ca_in_w, ca_in_b, q2, NTOK, CC, CC, 3 * CC, 0.17677669529663687f);

    // cross attention
    ca_attn<<<BW_ * NH_, 256>>>();

    // ca out projection
    sgemm<EPI_NONE><<<dim3(4, 196), 256>>>(co1, ca_out_w, ca_out_b, co2, NTOK, CC, CC, CC, 0.f);

    // LN2 + fold+roll + residual
    ca_ln2<<<NTOK, 256>>>(ln2_g, ln2_b);

    // FFN
    sgemm<EPI_GELU><<<dim3(16, 196), 256>>>(sk2, ff_w1, ff_b1, ffh, NTOK, 4 * CC, CC, 4 * CC, 0.f);
    sgemm<EPI_NONE><<<dim3(4, 196), 256>>>(ffh, ff_w2, ff_b2, ffo, NTOK, CC, 4 * CC, CC, 0.f);

    // LN3 + final residual, transpose to [B,C,H,W]
    final_kernel<<<BB * HWSZ, 256>>>(out, ln3_g, ln3_b);
}

// round 3
// speedup vs baseline: 2.1812x; 2.1812x over previous
#include <cuda_runtime.h>
#include <math.h>
#include <stdint.h>

// Problem constants
#define BB    8
#define CC    512
#define HH    56
#define WW_   56
#define HWSZ  3136
#define WS_   7
#define SS_   3
#define NH_   16
#define HD_   32
#define T_    49
#define NW_   64
#define BW_   512          // BB * NW_
#define NTOK  25088        // BW_ * T_
#define L_    64

// ---------------- scratch (device globals; no runtime alloc) ----------------
__device__ float g_vin [512 * 256];         // tf32-rounded vector input
__device__ float g_vec [BW_ * CC];          // gelu(vector@tm_w+b) (tf32-rounded)
__device__ float g_tok [NTOK * CC];         // unfolded rolled visual (tf32)
__device__ float g_qkv [NTOK * 3 * CC];
__device__ float g_o1  [NTOK * CC];         // window-attn out (tf32)
__device__ float g_w2  [NTOK * CC];
__device__ float g_skipa[NTOK * CC];        // skip1 [B,HW,C] full fp32
__device__ float g_pq  [NTOK * CC];         // CA query tokens (tf32)
__device__ float g_q2  [NTOK * CC];
__device__ float g_k2  [BW_ * CC];
__device__ float g_v2  [BW_ * CC];
__device__ float g_co1 [NTOK * CC];         // (tf32)
__device__ float g_co2 [NTOK * CC];
__device__ float g_skip2[NTOK * CC];        // full fp32
__device__ float g_skip2r[NTOK * CC];       // tf32-rounded copy for GEMM
__device__ float g_ffh [NTOK * 4 * CC];     // (tf32 via epilogue)
__device__ float g_ffo [NTOK * CC];
__device__ float g_bias[NH_ * T_ * T_];

// transposed (and tf32-rounded) weights: [N, K] K-contiguous
__device__ float g_tmw_t  [512 * 256];
__device__ float g_qkvw_t [1536 * 512];
__device__ float g_wprw_t [512 * 512];
__device__ float g_cain_t [1536 * 512];
__device__ float g_caout_t[512 * 512];
__device__ float g_ff1_t  [2048 * 512];
__device__ float g_ff2_t  [512 * 2048];

// ---------------- helpers ----------------
__device__ __forceinline__ float gelu_exact(float x) {
    return 0.5f * x * (1.0f + erff(x * 0.70710678118654752f));
}
__device__ __forceinline__ float tf32r(float x) {
    uint32_t o;
    asm("cvt.rna.tf32.f32 %0, %1;" : "=r"(o) : "f"(x));
    return __uint_as_float(o);
}
__device__ __forceinline__ uint32_t s2u(const void* p) {
    uint32_t a;
    asm("{ .reg .u64 t; cvta.to.shared.u64 t, %1; cvt.u32.u64 %0, t; }"
        : "=r"(a) : "l"(p));
    return a;
}

__device__ __forceinline__ void block_meanvar(float s, float ss, int n,
                                              float* mu, float* rstd) {
    #pragma unroll
    for (int o = 16; o > 0; o >>= 1) {
        s  += __shfl_down_sync(0xffffffffu, s,  o);
        ss += __shfl_down_sync(0xffffffffu, ss, o);
    }
    __shared__ float rs[8], rss[8], res[2];
    int lane = threadIdx.x & 31, wid = threadIdx.x >> 5;
    if (lane == 0) { rs[wid] = s; rss[wid] = ss; }
    __syncthreads();
    if (threadIdx.x == 0) {
        float S = 0.f, SS2 = 0.f;
        #pragma unroll
        for (int i = 0; i < 8; i++) { S += rs[i]; SS2 += rss[i]; }
        float m = S / n;
        float var = SS2 / n - m * m;
        res[0] = m; res[1] = rsqrtf(var + 1e-5f);
    }
    __syncthreads();
    *mu = res[0]; *rstd = res[1];
}

// ---------------- tf32 mma.sync GEMM ----------------
// C[M,N] = epi(A[M,K] @ W[N,K]^T + bias), all tf32-rounded inputs.
// M%128==0, N%128==0, K%32==0.
// 256 threads, 128x128 tile, K-chunk 32, double-buffered cp.async.
// Warp layout: 4 (M) x 2 (N); each warp 32x64 via m16n8k8 frags (2x8).
#define EPI_NONE  0
#define EPI_GELU  1
#define EPI_SCALE 2

#define LDPAD 36                    // smem row stride in floats
#define TILEF (128 * LDPAD)         // floats per tile buffer
#define TGEMM_SMEM (4 * TILEF * 4)  // 2 A bufs + 2 B bufs, bytes (73728)

__device__ __forceinline__ void mma_tf32(float* c, const uint32_t* a,
                                         const uint32_t* b) {
    asm volatile(
        "mma.sync.aligned.m16n8k8.row.col.f32.tf32.tf32.f32 "
        "{%0,%1,%2,%3}, {%4,%5,%6,%7}, {%8,%9}, {%0,%1,%2,%3};"
        : "+f"(c[0]), "+f"(c[1]), "+f"(c[2]), "+f"(c[3])
        : "r"(a[0]), "r"(a[1]), "r"(a[2]), "r"(a[3]),
          "r"(b[0]), "r"(b[1]));
}

template <int EPI>
__global__ __launch_bounds__(256)
void tgemm(const float* __restrict__ A, const float* __restrict__ W,
           const float* __restrict__ bias, float* __restrict__ C,
           int M, int N, int K, float alpha) {
    extern __shared__ float smem[];
    float* Abuf = smem;                 // [2][128][LDPAD]
    float* Bbuf = smem + 2 * TILEF;     // [2][128][LDPAD]
    const uint32_t sm_a = s2u(Abuf), sm_b = s2u(Bbuf);

    const int tid = threadIdx.x;
    const int wid = tid >> 5, lane = tid & 31;
    const int m0 = blockIdx.y << 7, n0 = blockIdx.x << 7;
    const int wm = wid & 3, wn = wid >> 2;
    const int m_off = wm << 5;          // 32-row warp tile
    const int n_off = wn << 6;          // 64-col warp tile

    const float* Abase = A + (size_t)m0 * K;
    const float* Wbase = W + (size_t)n0 * K;
    const int NC = K >> 5;

    const int seg = tid & 7;            // 8 x 16B segments per 32-float row
    const int lr0 = tid >> 3;           // 0..31

    auto load_chunk = [&](int c, int sel) {
        uint32_t ab = sm_a + sel * (TILEF * 4);
        uint32_t bb = sm_b + sel * (TILEF * 4);
        const float* As = Abase + c * 32 + seg * 4;
        const float* Ws = Wbase + c * 32 + seg * 4;
        #pragma unroll
        for (int i = 0; i < 4; i++) {
            int r = lr0 + (i << 5);
            uint32_t so = (uint32_t)(r * (LDPAD * 4) + seg * 16);
            asm volatile("cp.async.cg.shared.global [%0], [%1], 16;"
                         :: "r"(ab + so), "l"(As + (size_t)r * K));
            asm volatile("cp.async.cg.shared.global [%0], [%1], 16;"
                         :: "r"(bb + so), "l"(Ws + (size_t)r * K));
        }
    };

    float acc[2][8][4];
    #pragma unroll
    for (int i = 0; i < 2; i++)
        #pragma unroll
        for (int j = 0; j < 8; j++)
            #pragma unroll
            for (int q = 0; q < 4; q++) acc[i][j][q] = 0.f;

    load_chunk(0, 0);
    asm volatile("cp.async.commit_group;" ::: "memory");

    const int qr = lane >> 2, qc = lane & 3;

    for (int c = 0; c < NC; c++) {
        int sel = c & 1;
        if (c + 1 < NC) {
            load_chunk(c + 1, sel ^ 1);
            asm volatile("cp.async.commit_group;" ::: "memory");
            asm volatile("cp.async.wait_group 1;" ::: "memory");
        } else {
            asm volatile("cp.async.wait_group 0;" ::: "memory");
        }
        __syncthreads();

        const float* As = Abuf + sel * TILEF;
        const float* Bs = Bbuf + sel * TILEF;

        #pragma unroll
        for (int k0 = 0; k0 < 32; k0 += 8) {
            uint32_t a[2][4], b[8][2];
            #pragma unroll
            for (int mt = 0; mt < 2; mt++) {
                const float* ap = As + (m_off + mt * 16 + qr) * LDPAD + k0 + qc;
                a[mt][0] = __float_as_uint(ap[0]);
                a[mt][1] = __float_as_uint(ap[8 * LDPAD]);
                a[mt][2] = __float_as_uint(ap[4]);
                a[mt][3] = __float_as_uint(ap[8 * LDPAD + 4]);
            }
            #pragma unroll
            for (int nt = 0; nt < 8; nt++) {
                const float* bp = Bs + (n_off + nt * 8 + qr) * LDPAD + k0 + qc;
                b[nt][0] = __float_as_uint(bp[0]);
                b[nt][1] = __float_as_uint(bp[4]);
            }
            #pragma unroll
            for (int mt = 0; mt < 2; mt++)
                #pragma unroll
                for (int nt = 0; nt < 8; nt++)
                    mma_tf32(acc[mt][nt], a[mt], b[nt]);
        }
        __syncthreads();
    }

    // epilogue
    #pragma unroll
    for (int mt = 0; mt < 2; mt++) {
        #pragma unroll
        for (int half = 0; half < 2; half++) {
            int row = m0 + m_off + mt * 16 + qr + half * 8;
            float* Cp = C + (size_t)row * N + n0 + n_off;
            #pragma unroll
            for (int nt = 0; nt < 8; nt++) {
                int col = nt * 8 + qc * 2;
                float v0 = acc[mt][nt][half * 2 + 0] + bias[n0 + n_off + col];
                float v1 = acc[mt][nt][half * 2 + 1] + bias[n0 + n_off + col + 1];
                if (EPI == EPI_GELU)  { v0 = tf32r(gelu_exact(v0)); v1 = tf32r(gelu_exact(v1)); }
                if (EPI == EPI_SCALE) { v0 *= alpha; v1 *= alpha; }
                *(float2*)(Cp + col) = make_float2(v0, v1);
            }
        }
    }
}

// ---------------- weight transpose + tf32 round:  Wt[n,k] = rna(W[k,n]) ----
__global__ __launch_bounds__(256)
void transpose_w(const float* __restrict__ W, float* __restrict__ Wt,
                 int K, int N) {
    __shared__ float tile[32][33];
    int kb = blockIdx.y * 32, nb = blockIdx.x * 32;
    int tx = threadIdx.x & 31, ty = threadIdx.x >> 5;   // 32 x 8
    #pragma unroll
    for (int i = 0; i < 32; i += 8)
        tile[ty + i][tx] = W[(size_t)(kb + ty + i) * N + nb + tx];
    __syncthreads();
    #pragma unroll
    for (int i = 0; i < 32; i += 8)
        Wt[(size_t)(nb + ty + i) * K + kb + tx] = tf32r(tile[tx][ty + i]);
}

__global__ void round_copy(const float* __restrict__ in, float* __restrict__ o, int n) {
    int i = blockIdx.x * 256 + threadIdx.x;
    if (i < n) o[i] = tf32r(in[i]);
}

// ---------------- relative-position bias precompute ----------------
__global__ void bias_kernel(const float* __restrict__ w1, const float* __restrict__ b1,
                            const float* __restrict__ w2, const float* __restrict__ b2) {
    int pair = blockIdx.x;
    int q = pair / T_, k = pair % T_;
    float d0 = (float)(q / WS_ - k / WS_);
    float d1 = (float)(q % WS_ - k % WS_);
    float r0 = (d0 > 0.f ? 1.f : (d0 < 0.f ? -1.f : 0.f)) * log1pf(fabsf(d0));
    float r1 = (d1 > 0.f ? 1.f : (d1 < 0.f ? -1.f : 0.f)) * log1pf(fabsf(d1));
    int tid = threadIdx.x;
    __shared__ float hbuf[256];
    float hv = r0 * w1[tid] + r1 * w1[256 + tid] + b1[tid];
    hbuf[tid] = fmaxf(hv, 0.f);
    __syncthreads();
    if (tid < NH_) {
        float s = b2[tid];
        #pragma unroll 8
        for (int j = 0; j < 256; j++) s += hbuf[j] * w2[j * NH_ + tid];
        g_bias[tid * (T_ * T_) + pair] = s;
    }
}

// ---------------- roll(-3,-3) + unfold into token rows (tf32) ---------------
__global__ __launch_bounds__(256)
void unfold_kernel(const float* __restrict__ visual) {
    int r = blockIdx.x;
    int bw = r / T_, t = r % T_;
    int b = bw / NW_, win = bw % NW_, wh = win >> 3, ww = win & 7;
    int h = (wh * WS_ + t / WS_ + SS_) % HH;
    int w = (ww * WS_ + t % WS_ + SS_) % WW_;
    int hw = h * WW_ + w;
    for (int c = threadIdx.x; c < CC; c += 256)
        g_tok[(size_t)r * CC + c] = tf32r(visual[(size_t)(b * CC + c) * HWSZ + hw]);
}

// ---------------- window attention ----------------
__global__ __launch_bounds__(256)
void win_attn(const float* __restrict__ tau) {
    int bw = blockIdx.x >> 4;
    int hh = blockIdx.x & 15;
    int tid = threadIdx.x;

    __shared__ float sq[T_ * HD_], sk[T_ * HD_], sv[T_ * HD_];
    __shared__ float ss[T_ * 50];
    __shared__ float nq[T_], nk[T_];
    __shared__ int   rg[T_];

    size_t base = (size_t)(bw * T_) * (3 * CC);
    for (int idx = tid; idx < T_ * HD_; idx += 256) {
        int t = idx / HD_, d = idx % HD_;
        size_t ro = base + (size_t)t * (3 * CC) + hh * HD_ + d;
        sq[idx] = g_qkv[ro];
        sk[idx] = g_qkv[ro + CC];
        sv[idx] = g_qkv[ro + 2 * CC];
    }
    int win = bw & 63, wh = win >> 3, ww = win & 7;
    if (tid < T_) {
        int row = wh * WS_ + tid / WS_;
        int col = ww * WS_ + tid % WS_;
        int rh = row < 49 ? 0 : (row < 53 ? 1 : 2);
        int rw = col < 49 ? 0 : (col < 53 ? 1 : 2);
        rg[tid] = rh * 3 + rw;
    }
    __syncthreads();

    if (tid < T_) {
        float s1 = 0.f, s2 = 0.f;
        #pragma unroll
        for (int d = 0; d < HD_; d++) {
            float a = sq[tid * HD_ + d], b = sk[tid * HD_ + d];
            s1 += a * a; s2 += b * b;
        }
        nq[tid] = sqrtf(s1); nk[tid] = sqrtf(s2);
    }
    __syncthreads();

    float tauh = fmaxf(tau[hh], 0.01f);
    const float* bh = &g_bias[hh * (T_ * T_)];
    for (int idx = tid; idx < T_ * T_; idx += 256) {
        int q = idx / T_, k = idx % T_;
        float dot = 0.f;
        #pragma unroll
        for (int d = 0; d < HD_; d++) dot += sq[q * HD_ + d] * sk[k * HD_ + d];
        float s = dot / fmaxf(nq[q] * nk[k], 1e-6f) / tauh + bh[idx];
        if (rg[q] != rg[k]) s -= 100.0f;
        ss[q * 50 + k] = s;
    }
    __syncthreads();

    if (tid < T_) {
        float m = -1e30f;
        for (int k = 0; k < T_; k++) m = fmaxf(m, ss[tid * 50 + k]);
        float sum = 0.f;
        for (int k = 0; k < T_; k++) {
            float e = expf(ss[tid * 50 + k] - m);
            ss[tid * 50 + k] = e; sum += e;
        }
        float inv = 1.f / sum;
        for (int k = 0; k < T_; k++) ss[tid * 50 + k] *= inv;
    }
    __syncthreads();

    for (int idx = tid; idx < T_ * HD_; idx += 256) {
        int t = idx / HD_, d = idx % HD_;
        float acc = 0.f;
        #pragma unroll
        for (int k = 0; k < T_; k++) acc += ss[t * 50 + k] * sv[k * HD_ + d];
        g_o1[(size_t)(bw * T_ + t) * CC + hh * HD_ + d] = tf32r(acc);
    }
}

// ---------------- fold+roll(+3) + LN1 + residual; emit CA query tokens ------
__global__ __launch_bounds__(256)
void merge_ln1(const float* __restrict__ visual,
               const float* __restrict__ g, const float* __restrict__ bt) {
    int pos = blockIdx.x;
    int b = pos / HWSZ, hw = pos % HWSZ;
    int h = hw / WW_, w = hw % WW_;
    int hp = (h + HH - SS_) % HH, wp = (w + WW_ - SS_) % WW_;
    int rm = (b * NW_ + (hp / WS_) * 8 + (wp / WS_)) * T_ + (hp % WS_) * WS_ + (wp % WS_);

    __shared__ float x[CC];
    int tid = threadIdx.x;
    float s = 0.f, ss2 = 0.f;
    for (int c = tid; c < CC; c += 256) {
        float v = g_w2[(size_t)rm * CC + c];
        x[c] = v; s += v; ss2 += v * v;
    }
    float mu, rstd;
    block_meanvar(s, ss2, CC, &mu, &rstd);
    for (int c = tid; c < CC; c += 256) {
        float v = (x[c] - mu) * rstd * g[c] + bt[c]
                + visual[(size_t)(b * CC + c) * HWSZ + hw];
        g_skipa[(size_t)pos * CC + c] = v;
        g_pq  [(size_t)rm  * CC + c] = tf32r(v);
    }
}

// ---------------- cross attention ----------------
__global__ __launch_bounds__(256)
void ca_attn() {
    int bw = blockIdx.x >> 4;
    int hh = blockIdx.x & 15;
    int bkv = bw & 7;
    int tid = threadIdx.x;

    __shared__ float sq[T_ * HD_], sk[L_ * HD_], sv[L_ * HD_];
    __shared__ float ss[T_ * 65];

    for (int idx = tid; idx < T_ * HD_; idx += 256) {
        int t = idx / HD_, d = idx % HD_;
        sq[idx] = g_q2[(size_t)(bw * T_ + t) * CC + hh * HD_ + d];
    }
    for (int idx = tid; idx < L_ * HD_; idx += 256) {
        int l = idx / HD_, d = idx % HD_;
        size_t ro = (size_t)(bkv * L_ + l) * CC + hh * HD_ + d;
        sk[idx] = g_k2[ro];
        sv[idx] = g_v2[ro];
    }
    __syncthreads();

    for (int idx = tid; idx < T_ * L_; idx += 256) {
        int q = idx / L_, l = idx % L_;
        float dot = 0.f;
        #pragma unroll
        for (int d = 0; d < HD_; d++) dot += sq[q * HD_ + d] * sk[l * HD_ + d];
        ss[q * 65 + l] = dot;
    }
    __syncthreads();

    if (tid < T_) {
        float m = -1e30f;
        for (int l = 0; l < L_; l++) m = fmaxf(m, ss[tid * 65 + l]);
        float sum = 0.f;
        for (int l = 0; l < L_; l++) {
            float e = expf(ss[tid * 65 + l] - m);
            ss[tid * 65 + l] = e; sum += e;
        }
        float inv = 1.f / sum;
        for (int l = 0; l < L_; l++) ss[tid * 65 + l] *= inv;
    }
    __syncthreads();

    for (int idx = tid; idx < T_ * HD_; idx += 256) {
        int t = idx / HD_, d = idx % HD_;
        float acc = 0.f;
        #pragma unroll
        for (int l = 0; l < L_; l++) acc += ss[t * 65 + l] * sv[l * HD_ + d];
        g_co1[(size_t)(bw * T_ + t) * CC + hh * HD_ + d] = tf32r(acc);
    }
}

// ---------------- LN2 + fold+roll(+3) + residual ----------------
__global__ __launch_bounds__(256)
void ca_ln2(const float* __restrict__ g, const float* __restrict__ bt) {
    int r = blockIdx.x;
    int bw = r / T_, t = r % T_;
    int b = bw / NW_, win = bw % NW_, wh = win >> 3, ww = win & 7;
    int h = (wh * WS_ + t / WS_ + SS_) % HH;
    int w = (ww * WS_ + t % WS_ + SS_) % WW_;
    int pos = b * HWSZ + h * WW_ + w;

    __shared__ float x[CC];
    int tid = threadIdx.x;
    float s = 0.f, ss2 = 0.f;
    for (int c = tid; c < CC; c += 256) {
        float v = g_co2[(size_t)r * CC + c];
        x[c] = v; s += v; ss2 += v * v;
    }
    float mu, rstd;
    block_meanvar(s, ss2, CC, &mu, &rstd);
    for (int c = tid; c < CC; c += 256) {
        float v = (x[c] - mu) * rstd * g[c] + bt[c]
                + g_skipa[(size_t)pos * CC + c];
        g_skip2 [(size_t)pos * CC + c] = v;
        g_skip2r[(size_t)pos * CC + c] = tf32r(v);
    }
}

// ---------------- LN3(ff) + skip2, write [B,C,H,W] ----------------
__global__ __launch_bounds__(256)
void final_kernel(float* __restrict__ out,
                  const float* __restrict__ g, const float* __restrict__ bt) {
    int pos = blockIdx.x;
    int b = pos / HWSZ, hw = pos % HWSZ;

    __shared__ float x[CC];
    int tid = threadIdx.x;
    float s = 0.f, ss2 = 0.f;
    for (int c = tid; c < CC; c += 256) {
        float v = g_ffo[(size_t)pos * CC + c];
        x[c] = v; s += v; ss2 += v * v;
    }
    float mu, rstd;
    block_meanvar(s, ss2, CC, &mu, &rstd);
    for (int c = tid; c < CC; c += 256) {
        float v = (x[c] - mu) * rstd * g[c] + bt[c];
        out[(size_t)(b * CC + c) * HWSZ + hw] = g_skip2[(size_t)pos * CC + c] + v;
    }
}

// ---------------- launch ----------------
extern "C" void kernel_launch(void* const* d_in, const int* in_sizes, int n_in,
                              void* d_out, int out_size) {
    const float* visual   = (const float*)d_in[0];
    const float* vector   = (const float*)d_in[1];
    const float* tm_w     = (const float*)d_in[2];
    const float* tm_b     = (const float*)d_in[3];
    const float* ln1_g    = (const float*)d_in[4];
    const float* ln1_b    = (const float*)d_in[5];
    const float* ln2_g    = (const float*)d_in[6];
    const float* ln2_b    = (const float*)d_in[7];
    const float* ln3_g    = (const float*)d_in[8];
    const float* ln3_b    = (const float*)d_in[9];
    const float* qkv_w    = (const float*)d_in[10];
    const float* qkv_b    = (const float*)d_in[11];
    const float* wproj_w  = (const float*)d_in[12];
    const float* wproj_b  = (const float*)d_in[13];
    const float* meta_w1  = (const float*)d_in[14];
    const float* meta_b1  = (const float*)d_in[15];
    const float* meta_w2  = (const float*)d_in[16];
    const float* meta_b2  = (const float*)d_in[17];
    const float* tau      = (const float*)d_in[18];
    const float* ca_in_w  = (const float*)d_in[19];
    const float* ca_in_b  = (const float*)d_in[20];
    const float* ca_out_w = (const float*)d_in[21];
    const float* ca_out_b = (const float*)d_in[22];
    const float* ff_w1    = (const float*)d_in[23];
    const float* ff_b1    = (const float*)d_in[24];
    const float* ff_w2    = (const float*)d_in[25];
    const float* ff_b2    = (const float*)d_in[26];
    float* out = (float*)d_out;

    float *vin, *vec, *tok, *qkv, *o1, *w2, *pq, *q2, *k2, *v2, *co1, *co2,
          *sk2r, *ffh, *ffo;
    float *tmwt, *qkvwt, *wprwt, *caint, *caoutt, *ff1t, *ff2t;
    cudaGetSymbolAddress((void**)&vin,   g_vin);
    cudaGetSymbolAddress((void**)&vec,   g_vec);
    cudaGetSymbolAddress((void**)&tok,   g_tok);
    cudaGetSymbolAddress((void**)&qkv,   g_qkv);
    cudaGetSymbolAddress((void**)&o1,    g_o1);
    cudaGetSymbolAddress((void**)&w2,    g_w2);
    cudaGetSymbolAddress((void**)&pq,    g_pq);
    cudaGetSymbolAddress((void**)&q2,    g_q2);
    cudaGetSymbolAddress((void**)&k2,    g_k2);
    cudaGetSymbolAddress((void**)&v2,    g_v2);
    cudaGetSymbolAddress((void**)&co1,   g_co1);
    cudaGetSymbolAddress((void**)&co2,   g_co2);
    cudaGetSymbolAddress((void**)&sk2r,  g_skip2r);
    cudaGetSymbolAddress((void**)&ffh,   g_ffh);
    cudaGetSymbolAddress((void**)&ffo,   g_ffo);
    cudaGetSymbolAddress((void**)&tmwt,  g_tmw_t);
    cudaGetSymbolAddress((void**)&qkvwt, g_qkvw_t);
    cudaGetSymbolAddress((void**)&wprwt, g_wprw_t);
    cudaGetSymbolAddress((void**)&caint, g_cain_t);
    cudaGetSymbolAddress((void**)&caoutt,g_caout_t);
    cudaGetSymbolAddress((void**)&ff1t,  g_ff1_t);
    cudaGetSymbolAddress((void**)&ff2t,  g_ff2_t);

    cudaFuncSetAttribute(tgemm<EPI_NONE>,  cudaFuncAttributeMaxDynamicSharedMemorySize, TGEMM_SMEM);
    cudaFuncSetAttribute(tgemm<EPI_GELU>,  cudaFuncAttributeMaxDynamicSharedMemorySize, TGEMM_SMEM);
    cudaFuncSetAttribute(tgemm<EPI_SCALE>, cudaFuncAttributeMaxDynamicSharedMemorySize, TGEMM_SMEM);

    // weight transposes (+tf32 rounding)
    transpose_w<<<dim3(16,  8), 256>>>(tm_w,     tmwt,  256,  512);
    transpose_w<<<dim3(48, 16), 256>>>(qkv_w,    qkvwt, 512, 1536);
    transpose_w<<<dim3(16, 16), 256>>>(wproj_w,  wprwt, 512,  512);
    transpose_w<<<dim3(48, 16), 256>>>(ca_in_w,  caint, 512, 1536);
    transpose_w<<<dim3(16, 16), 256>>>(ca_out_w, caoutt,512,  512);
    transpose_w<<<dim3(64, 16), 256>>>(ff_w1,    ff1t,  512, 2048);
    transpose_w<<<dim3(16, 64), 256>>>(ff_w2,    ff2t, 2048,  512);
    round_copy<<<512, 256>>>(vector, vin, 512 * 256);

    bias_kernel<<<T_ * T_, 256>>>(meta_w1, meta_b1, meta_w2, meta_b2);

    // vec = gelu(vector @ tm_w + tm_b)
    tgemm<EPI_GELU><<<dim3(4, 4), 256, TGEMM_SMEM>>>(vin, tmwt, tm_b, vec, 512, 512, 256, 0.f);
    // K2/V2 (only B distinct kv sets)
    tgemm<EPI_NONE><<<dim3(4, 4), 256, TGEMM_SMEM>>>(vec, caint + 512 * 512,  ca_in_b + 512,  k2, 512, 512, 512, 0.f);
    tgemm<EPI_NONE><<<dim3(4, 4), 256, TGEMM_SMEM>>>(vec, caint + 1024 * 512, ca_in_b + 1024, v2, 512, 512, 512, 0.f);

    unfold_kernel<<<NTOK, 256>>>(visual);
    tgemm<EPI_NONE><<<dim3(12, 196), 256, TGEMM_SMEM>>>(tok, qkvwt, qkv_b, qkv, NTOK, 3 * CC, CC, 0.f);
    win_attn<<<BW_ * NH_, 256>>>(tau);
    tgemm<EPI_NONE><<<dim3(4, 196), 256, TGEMM_SMEM>>>(o1, wprwt, wproj_b, w2, NTOK, CC, CC, 0.f);
    merge_ln1<<<BB * HWSZ, 256>>>(visual, ln1_g, ln1_b);
    tgemm<EPI_SCALE><<<dim3(4, 196), 256, TGEMM_SMEM>>>(pq, caint, ca_in_b, q2, NTOK, CC, CC, 0.17677669529663687f);
    ca_attn<<<BW_ * NH_, 256>>>();
    tgemm<EPI_NONE><<<dim3(4, 196), 256, TGEMM_SMEM>>>(co1, caoutt, ca_out_b, co2, NTOK, CC, CC, 0.f);
    ca_ln2<<<NTOK, 256>>>(ln2_g, ln2_b);
    tgemm<EPI_GELU><<<dim3(16, 196), 256, TGEMM_SMEM>>>(sk2r, ff1t, ff_b1, ffh, NTOK, 4 * CC, CC, 0.f);
    tgemm<EPI_NONE><<<dim3(4, 196), 256, TGEMM_SMEM>>>(ffh, ff2t, ff_b2, ffo, NTOK, CC, 2048, 0.f);
    final_kernel<<<BB * HWSZ, 256>>>(out, ln3_g, ln3_b);
}